// round 11
// baseline (speedup 1.0000x reference)
// ChromDropout — GB300 (sm_103a). CONVERGED — reverted to R6 best (354.5 us).
//
// out[b,g] = x[b,g] * keep[b, chrom_ids[g]] * 5.75; per-row 4-of-23 chromosome
// drop reproduced bit-exactly from JAX partitionable threefry2x32 (key 42):
// fold_in(row) -> split -> random_bits(23) -> stable argsort -> first 4.
//
// Optimization history:
//   R2 381us  naive float4 stream (DRAM 83.3%)
//   R3 364us  MLP=4 front-batched loads + streaming hints (DRAM 88.3%)  [WIN]
//   R4 neutral VEC=8 — latency fully covered at MLP=4                   [falsified]
//   R5 354.5us single fused launch, smem mask per block (2 warps)       [WIN]
//   R6 354.5us TPB=512 + incremental indexing (DRAM 88.6%)              [neutral]
//   R8 384.9us persistent grid, per-warp mask recompute — issue-bound
//      (83.8% issue, ALU 56.6%) starved DRAM to 80%                     [REGRESSION]
// Floor: 2.50 GB mandatory traffic at the path-independent LTS chip cap
// (~7.04 TB/s NAT) = ~348 us kernel; total 354.5 us. Holding here.

#include <cuda_runtime.h>
#include <stdint.h>

#define BROWS 16384
#define GENES 19064
#define G4 (GENES / 4)          // 4766
#define NCHROM 23
#define NDROP 4
#define SCALE 5.75f             // 1 / (4/23)
#define TPB 512                 // threads per block
#define VEC 4                   // float4 per thread; block covers 2048 float4 (< G4 => <=2 rows)

// ---------------- threefry2x32 (exact JAX rounds, partitionable path) ----------------
__device__ __forceinline__ uint32_t rotl32(uint32_t x, int d) {
    return (x << d) | (x >> (32 - d));
}

__device__ __forceinline__ void threefry2x32(uint32_t k0, uint32_t k1,
                                             uint32_t x0, uint32_t x1,
                                             uint32_t& o0, uint32_t& o1) {
    uint32_t ks2 = k0 ^ k1 ^ 0x1BD11BDAu;
    x0 += k0; x1 += k1;
#define TF_RND(r) { x0 += x1; x1 = rotl32(x1, r); x1 ^= x0; }
    TF_RND(13) TF_RND(15) TF_RND(26) TF_RND(6)   x0 += k1;  x1 += ks2 + 1u;
    TF_RND(17) TF_RND(29) TF_RND(16) TF_RND(24)  x0 += ks2; x1 += k0  + 2u;
    TF_RND(13) TF_RND(15) TF_RND(26) TF_RND(6)   x0 += k0;  x1 += k1  + 3u;
    TF_RND(17) TF_RND(29) TF_RND(16) TF_RND(24)  x0 += k1;  x1 += ks2 + 4u;
    TF_RND(13) TF_RND(15) TF_RND(26) TF_RND(6)   x0 += ks2; x1 += k0  + 5u;
#undef TF_RND
    o0 = x0; o1 = x1;
}

// Warp-collective: 23-bit drop mask for `row`.
// lane j (<23) computes sort-key j; stable 4-smallest selection via
// redux-min + ballot (ties -> lowest lane, matching JAX stable argsort).
__device__ __forceinline__ unsigned warp_row_mask(unsigned row) {
    int lane = threadIdx.x & 31;

    uint32_t kb0, kb1, sk0, sk1;
    threefry2x32(0u, 42u, 0u, row, kb0, kb1);     // per-row key
    threefry2x32(kb0, kb1, 0u, 1u, sk0, sk1);     // split -> subkey

    uint32_t key = 0xFFFFFFFFu;
    if (lane < NCHROM) {
        uint32_t a, b;
        threefry2x32(sk0, sk1, 0u, (uint32_t)lane, a, b);
        key = a ^ b;                              // random_bits fold
    }

    unsigned drop = 0;
#pragma unroll
    for (int s = 0; s < NDROP; s++) {
        uint32_t mn   = __reduce_min_sync(0xFFFFFFFFu, key);
        unsigned ball = __ballot_sync(0xFFFFFFFFu, key == mn);
        int w = __ffs(ball) - 1;                  // lowest lane wins ties (stable)
        drop |= 1u << w;
        if (lane == w) key = 0xFFFFFFFFu;
    }
    return drop;
}

// ---------------- fused kernel: mask gen + streaming apply ----------------
__global__ void __launch_bounds__(TPB) fused_kernel(const float4* __restrict__ x,
                                                    const int4*   __restrict__ chrom4,
                                                    float4*       __restrict__ out) {
    __shared__ unsigned smask[2];

    unsigned blk_base = blockIdx.x * (TPB * VEC);
    unsigned base     = blk_base + threadIdx.x;
    unsigned first_b  = blk_base / G4;

    // Front-batch the streaming loads; mask compute hides under their latency.
    float4 v[VEC];
#pragma unroll
    for (int k = 0; k < VEC; k++)
        v[k] = __ldcs(&x[base + (unsigned)k * TPB]);

    int wid = threadIdx.x >> 5;
    if (wid < 2) {
        unsigned row = first_b + (unsigned)wid;
        if (row >= BROWS) row = BROWS - 1;        // clamp (overflow row unused)
        unsigned m = warp_row_mask(row);
        if ((threadIdx.x & 31) == 0) smask[wid] = m;
    }
    __syncthreads();

    unsigned m0 = smask[0], m1 = smask[1];

    // Incremental row/offset: one division for the first element, then
    // wrap-updates (ALU add/cmp instead of div per step).
    unsigned b0  = base / G4;
    unsigned g4  = base - b0 * G4;
    unsigned m   = (b0 == first_b) ? m0 : m1;

#pragma unroll
    for (int k = 0; k < VEC; k++) {
        int4 c = __ldg(&chrom4[g4]);              // L1/L2-resident 76KB table

        float4 w = v[k];
        w.x = ((m >> c.x) & 1u) ? 0.f : w.x * SCALE;
        w.y = ((m >> c.y) & 1u) ? 0.f : w.y * SCALE;
        w.z = ((m >> c.z) & 1u) ? 0.f : w.z * SCALE;
        w.w = ((m >> c.w) & 1u) ? 0.f : w.w * SCALE;
        __stcs(&out[base + (unsigned)k * TPB], w);

        g4 += TPB;                                // advance within row, wrap at G4
        if (g4 >= G4) { g4 -= G4; m = m1; }       // crossed the row boundary
    }
}

extern "C" void kernel_launch(void* const* d_in, const int* in_sizes, int n_in,
                              void* d_out, int out_size) {
    const float* x         = (const float*)d_in[0];
    const int*   chrom_ids = (const int*)d_in[1];
    float*       out       = (float*)d_out;

    // B*G/4 float4 elements = 78,086,144 = 2048 * 38,128 (tail-free)
    unsigned n4 = (unsigned)BROWS * (unsigned)G4;
    fused_kernel<<<n4 / (TPB * VEC), TPB>>>((const float4*)x,
                                            (const int4*)chrom_ids,
                                            (float4*)out);
}

// round 12
// speedup vs baseline: 1.0055x; 1.0055x over previous
// ChromDropout — GB300 (sm_103a). CONVERGED — reverted to R6 best (354.5 us).
//
// out[b,g] = x[b,g] * keep[b, chrom_ids[g]] * 5.75; per-row 4-of-23 chromosome
// drop reproduced bit-exactly from JAX partitionable threefry2x32 (key 42):
// fold_in(row) -> split -> random_bits(23) -> stable argsort -> first 4.
//
// Optimization history:
//   R2 381us  naive float4 stream (DRAM 83.3%)
//   R3 364us  MLP=4 front-batched loads + streaming hints (DRAM 88.3%)  [WIN]
//   R4 neutral VEC=8 — latency fully covered at MLP=4                   [falsified]
//   R5 354.5us single fused launch, smem mask per block (2 warps)       [WIN]
//   R6 354.5us TPB=512 + incremental indexing (DRAM 88.6%)              [neutral]
//   R8 384.9us persistent grid, per-warp mask recompute — issue-bound
//      (83.8% issue, ALU 56.6%) starved DRAM to 80%                     [REGRESSION]
// Floor: 2.50 GB mandatory traffic at the path-independent LTS chip cap
// (~7.04 TB/s NAT) = ~348 us kernel; total 354.5 us. Holding here.

#include <cuda_runtime.h>
#include <stdint.h>

#define BROWS 16384
#define GENES 19064
#define G4 (GENES / 4)          // 4766
#define NCHROM 23
#define NDROP 4
#define SCALE 5.75f             // 1 / (4/23)
#define TPB 512                 // threads per block
#define VEC 4                   // float4 per thread; block covers 2048 float4 (< G4 => <=2 rows)

// ---------------- threefry2x32 (exact JAX rounds, partitionable path) ----------------
__device__ __forceinline__ uint32_t rotl32(uint32_t x, int d) {
    return (x << d) | (x >> (32 - d));
}

__device__ __forceinline__ void threefry2x32(uint32_t k0, uint32_t k1,
                                             uint32_t x0, uint32_t x1,
                                             uint32_t& o0, uint32_t& o1) {
    uint32_t ks2 = k0 ^ k1 ^ 0x1BD11BDAu;
    x0 += k0; x1 += k1;
#define TF_RND(r) { x0 += x1; x1 = rotl32(x1, r); x1 ^= x0; }
    TF_RND(13) TF_RND(15) TF_RND(26) TF_RND(6)   x0 += k1;  x1 += ks2 + 1u;
    TF_RND(17) TF_RND(29) TF_RND(16) TF_RND(24)  x0 += ks2; x1 += k0  + 2u;
    TF_RND(13) TF_RND(15) TF_RND(26) TF_RND(6)   x0 += k0;  x1 += k1  + 3u;
    TF_RND(17) TF_RND(29) TF_RND(16) TF_RND(24)  x0 += k1;  x1 += ks2 + 4u;
    TF_RND(13) TF_RND(15) TF_RND(26) TF_RND(6)   x0 += ks2; x1 += k0  + 5u;
#undef TF_RND
    o0 = x0; o1 = x1;
}

// Warp-collective: 23-bit drop mask for `row`.
// lane j (<23) computes sort-key j; stable 4-smallest selection via
// redux-min + ballot (ties -> lowest lane, matching JAX stable argsort).
__device__ __forceinline__ unsigned warp_row_mask(unsigned row) {
    int lane = threadIdx.x & 31;

    uint32_t kb0, kb1, sk0, sk1;
    threefry2x32(0u, 42u, 0u, row, kb0, kb1);     // per-row key
    threefry2x32(kb0, kb1, 0u, 1u, sk0, sk1);     // split -> subkey

    uint32_t key = 0xFFFFFFFFu;
    if (lane < NCHROM) {
        uint32_t a, b;
        threefry2x32(sk0, sk1, 0u, (uint32_t)lane, a, b);
        key = a ^ b;                              // random_bits fold
    }

    unsigned drop = 0;
#pragma unroll
    for (int s = 0; s < NDROP; s++) {
        uint32_t mn   = __reduce_min_sync(0xFFFFFFFFu, key);
        unsigned ball = __ballot_sync(0xFFFFFFFFu, key == mn);
        int w = __ffs(ball) - 1;                  // lowest lane wins ties (stable)
        drop |= 1u << w;
        if (lane == w) key = 0xFFFFFFFFu;
    }
    return drop;
}

// ---------------- fused kernel: mask gen + streaming apply ----------------
__global__ void __launch_bounds__(TPB) fused_kernel(const float4* __restrict__ x,
                                                    const int4*   __restrict__ chrom4,
                                                    float4*       __restrict__ out) {
    __shared__ unsigned smask[2];

    unsigned blk_base = blockIdx.x * (TPB * VEC);
    unsigned base     = blk_base + threadIdx.x;
    unsigned first_b  = blk_base / G4;

    // Front-batch the streaming loads; mask compute hides under their latency.
    float4 v[VEC];
#pragma unroll
    for (int k = 0; k < VEC; k++)
        v[k] = __ldcs(&x[base + (unsigned)k * TPB]);

    int wid = threadIdx.x >> 5;
    if (wid < 2) {
        unsigned row = first_b + (unsigned)wid;
        if (row >= BROWS) row = BROWS - 1;        // clamp (overflow row unused)
        unsigned m = warp_row_mask(row);
        if ((threadIdx.x & 31) == 0) smask[wid] = m;
    }
    __syncthreads();

    unsigned m0 = smask[0], m1 = smask[1];

    // Incremental row/offset: one division for the first element, then
    // wrap-updates (ALU add/cmp instead of div per step).
    unsigned b0  = base / G4;
    unsigned g4  = base - b0 * G4;
    unsigned m   = (b0 == first_b) ? m0 : m1;

#pragma unroll
    for (int k = 0; k < VEC; k++) {
        int4 c = __ldg(&chrom4[g4]);              // L1/L2-resident 76KB table

        float4 w = v[k];
        w.x = ((m >> c.x) & 1u) ? 0.f : w.x * SCALE;
        w.y = ((m >> c.y) & 1u) ? 0.f : w.y * SCALE;
        w.z = ((m >> c.z) & 1u) ? 0.f : w.z * SCALE;
        w.w = ((m >> c.w) & 1u) ? 0.f : w.w * SCALE;
        __stcs(&out[base + (unsigned)k * TPB], w);

        g4 += TPB;                                // advance within row, wrap at G4
        if (g4 >= G4) { g4 -= G4; m = m1; }       // crossed the row boundary
    }
}

extern "C" void kernel_launch(void* const* d_in, const int* in_sizes, int n_in,
                              void* d_out, int out_size) {
    const float* x         = (const float*)d_in[0];
    const int*   chrom_ids = (const int*)d_in[1];
    float*       out       = (float*)d_out;

    // B*G/4 float4 elements = 78,086,144 = 2048 * 38,128 (tail-free)
    unsigned n4 = (unsigned)BROWS * (unsigned)G4;
    fused_kernel<<<n4 / (TPB * VEC), TPB>>>((const float4*)x,
                                            (const int4*)chrom_ids,
                                            (float4*)out);
}